// round 6
// baseline (speedup 1.0000x reference)
#include <cuda_runtime.h>

// y[m,n] = sum_k x[m,k] * (mask[n,k]*W[n,k]) + b[n]
// M=16384, K=2048, N=8192, fp32.
//
// Pipeline:
//  1. rowscan:    per output row n, 64-word k-bitmask + heavy flag (>=256 nnz)
//  2. tile_pack:  per 24-wide n-tile, union of non-heavy rows' bitmasks ->
//                 ordered k index list + packed PRE-SPLATTED weight panel
//  3. heavy_list: deterministic ordered list of heavy columns
//  4. transpose:  xT[k][m]  (spmm reads become coalesced)
//  5. spmm:       BARRIER-FREE gather GEMM over compacted K: no smem, x and W
//                 streamed through L1 via coalesced LDG.128, f32x2 FMAs
//  6. dense_cols: recompute heavy columns densely, overwrite their output

#define M_DIM 16384
#define K_DIM 2048
#define N_DIM 8192
#define TN 24
#define NTILES ((N_DIM + TN - 1) / TN)   // 342
#define TM 256
#define KPAD_ALIGN 4
#define HEAVY_THRESH 256

typedef unsigned long long ull;

// Static scratch (allocations are forbidden).
__device__ unsigned g_rowbits[(size_t)N_DIM * 64];            // 2 MB
__device__ int      g_heavyflag[N_DIM];
__device__ int      g_heavy[N_DIM];
__device__ int      g_nheavy;
__device__ int      g_kidx[NTILES * K_DIM];                   // 2.8 MB
__device__ int      g_kpad[NTILES];
__device__ float2   g_Wp2[(size_t)NTILES * K_DIM * TN];       // 134 MB, splatted
__device__ float    g_xT[(size_t)K_DIM * M_DIM];              // 128 MB

// ---------------------------------------------------------------------------
// helpers
// ---------------------------------------------------------------------------
__device__ __forceinline__ void fma2(ull& acc, ull a, ull b) {
    asm("fma.rn.f32x2 %0, %1, %2, %0;" : "+l"(acc) : "l"(a), "l"(b));
}
__device__ __forceinline__ void unpack2(ull a, float& lo, float& hi) {
    asm("mov.b64 {%0, %1}, %2;" : "=f"(lo), "=f"(hi) : "l"(a));
}

// ---------------------------------------------------------------------------
// 1. Per-row bitmask + heavy flag. One warp per output row.
// ---------------------------------------------------------------------------
__global__ void rowscan_kernel(const float* __restrict__ mask) {
    int warp = (blockIdx.x * blockDim.x + threadIdx.x) >> 5;
    int lane = threadIdx.x & 31;
    if (warp >= N_DIM) return;
    const float* row = mask + (size_t)warp * K_DIM;
    int cnt = 0;
    #pragma unroll 8
    for (int w = 0; w < K_DIM / 32; ++w) {
        float v = row[w * 32 + lane];
        unsigned b = __ballot_sync(0xffffffffu, v != 0.0f);
        if (lane == 0) g_rowbits[(size_t)warp * 64 + w] = b;
        cnt += __popc(b);
    }
    if (lane == 0) g_heavyflag[warp] = (cnt >= HEAVY_THRESH) ? 1 : 0;
}

// ---------------------------------------------------------------------------
// 2. Per n-tile: union bitmask (excluding heavy rows), ordered compaction,
//    packed pre-splatted masked weights.
// ---------------------------------------------------------------------------
__global__ void tile_pack_kernel(const float* __restrict__ W,
                                 const float* __restrict__ mask) {
    const int t = blockIdx.x, n0 = t * TN, tid = threadIdx.x;
    __shared__ unsigned words[64];
    __shared__ int cnts[64];
    __shared__ int hflag[TN];
    __shared__ int s_cnt, s_kpad;

    if (tid < TN)
        hflag[tid] = (n0 + tid < N_DIM) ? g_heavyflag[n0 + tid] : 1;
    __syncthreads();

    if (tid < 64) {
        unsigned u = 0;
        #pragma unroll 4
        for (int nn = 0; nn < TN; ++nn)
            if (!hflag[nn]) u |= g_rowbits[(size_t)(n0 + nn) * 64 + tid];
        words[tid] = u;
        cnts[tid] = __popc(u);
    }
    __syncthreads();

    if (tid < 64) {
        int base = 0;
        for (int u = 0; u < tid; ++u) base += cnts[u];
        unsigned wv = words[tid];
        int k0 = tid * 32;
        while (wv) {
            int b = __ffs(wv) - 1;
            wv &= wv - 1;
            g_kidx[t * K_DIM + base++] = k0 + b;
        }
    }
    if (tid == 0) {
        int cnt = 0;
        for (int u = 0; u < 64; ++u) cnt += cnts[u];
        int kpad = (cnt + KPAD_ALIGN - 1) / KPAD_ALIGN * KPAD_ALIGN;
        if (kpad == 0) kpad = KPAD_ALIGN;
        if (kpad > K_DIM) kpad = K_DIM;
        for (int j = cnt; j < kpad; ++j) g_kidx[t * K_DIM + j] = 0;
        s_cnt = cnt; s_kpad = kpad;
        g_kpad[t] = kpad;
    }
    __syncthreads();

    const int cnt = s_cnt, kpad = s_kpad;
    for (int e = tid; e < kpad * TN; e += blockDim.x) {
        int j  = e / TN;
        int nn = e - j * TN;
        float wv = 0.0f;
        if (j < cnt && !hflag[nn] && (n0 + nn) < N_DIM) {
            int k = g_kidx[t * K_DIM + j];
            size_t off = (size_t)(n0 + nn) * K_DIM + k;
            wv = mask[off] * W[off];
        }
        g_Wp2[((size_t)t * K_DIM + j) * TN + nn] = make_float2(wv, wv);
    }
}

// ---------------------------------------------------------------------------
// 3. Ordered heavy-column list (single block, deterministic).
// ---------------------------------------------------------------------------
__global__ void heavy_list_kernel() {
    const int tid = threadIdx.x;
    const int per = N_DIM / 256;  // 32
    __shared__ int cnt[256];
    __shared__ int off[257];
    int c = 0;
    for (int i = 0; i < per; ++i) c += g_heavyflag[tid * per + i];
    cnt[tid] = c;
    __syncthreads();
    if (tid == 0) {
        off[0] = 0;
        for (int i = 0; i < 256; ++i) off[i + 1] = off[i] + cnt[i];
        g_nheavy = off[256];
    }
    __syncthreads();
    int o = off[tid];
    for (int i = 0; i < per; ++i) {
        int n = tid * per + i;
        if (g_heavyflag[n]) g_heavy[o++] = n;
    }
}

// ---------------------------------------------------------------------------
// 4. Transpose x -> xT[k][m].
// ---------------------------------------------------------------------------
__global__ void transpose_kernel(const float* __restrict__ x,
                                 float* __restrict__ xT) {
    __shared__ float tile[32][33];
    const int k0 = blockIdx.x * 32;
    const int m0 = blockIdx.y * 32;
    const int tx = threadIdx.x, ty = threadIdx.y;   // 32 x 8
    #pragma unroll
    for (int j = 0; j < 32; j += 8)
        tile[ty + j][tx] = x[(size_t)(m0 + ty + j) * K_DIM + k0 + tx];
    __syncthreads();
    #pragma unroll
    for (int j = 0; j < 32; j += 8)
        xT[(size_t)(k0 + ty + j) * M_DIM + m0 + tx] = tile[tx][ty + j];
}

// ---------------------------------------------------------------------------
// 5. Main gather-GEMM over compacted K — barrier-free, no shared memory.
//    Block: 256m x 24n, 128 threads.
//    Warp w covers cols n0+6w..+5 ; lane l covers rows m0+4l..+3 and +128.
//    Per k: x = 2 coalesced LDG.128 ; w = 3 broadcast LDG.128 (pre-splatted).
// ---------------------------------------------------------------------------
__global__ void __launch_bounds__(128)
spmm_kernel(const float* __restrict__ xT,
            const float* __restrict__ bias,
            float* __restrict__ out) {
    const int t    = blockIdx.y;
    const int m0   = blockIdx.x * TM;
    const int n0   = t * TN;
    const int kpad = g_kpad[t];
    const int tid  = threadIdx.x;
    const int lane = tid & 31;
    const int warp = tid >> 5;

    ull acc[4][6];
    #pragma unroll
    for (int i = 0; i < 4; ++i)
        #pragma unroll
        for (int j = 0; j < 6; ++j) acc[i][j] = 0ull;

    const int* __restrict__ kidx = g_kidx + t * K_DIM;
    const ull* __restrict__ wbase =
        (const ull*)(g_Wp2 + (size_t)t * K_DIM * TN) + warp * 6;
    const float* __restrict__ xbase = xT + m0 + 4 * lane;

    // Process two k's per iteration: 10 independent LDG.128 in flight.
    for (int c = 0; c < kpad; c += 2) {
        int2 kk = *(const int2*)&kidx[c];

        const float* p0 = xbase + ((size_t)kk.x << 14);
        const float* p1 = xbase + ((size_t)kk.y << 14);
        ulonglong2 xa0 = *(const ulonglong2*)p0;
        ulonglong2 xb0 = *(const ulonglong2*)(p0 + 128);
        ulonglong2 xa1 = *(const ulonglong2*)p1;
        ulonglong2 xb1 = *(const ulonglong2*)(p1 + 128);

        const ull* w0 = wbase + (size_t)c * TN;
        const ull* w1 = w0 + TN;
        ulonglong2 wA0 = *(const ulonglong2*)(w0);
        ulonglong2 wA1 = *(const ulonglong2*)(w0 + 2);
        ulonglong2 wA2 = *(const ulonglong2*)(w0 + 4);
        ulonglong2 wB0 = *(const ulonglong2*)(w1);
        ulonglong2 wB1 = *(const ulonglong2*)(w1 + 2);
        ulonglong2 wB2 = *(const ulonglong2*)(w1 + 4);

        {
            ull xv[4] = {xa0.x, xa0.y, xb0.x, xb0.y};
            ull wv[6] = {wA0.x, wA0.y, wA1.x, wA1.y, wA2.x, wA2.y};
            #pragma unroll
            for (int i = 0; i < 4; ++i)
                #pragma unroll
                for (int j = 0; j < 6; ++j)
                    fma2(acc[i][j], xv[i], wv[j]);
        }
        {
            ull xv[4] = {xa1.x, xa1.y, xb1.x, xb1.y};
            ull wv[6] = {wB0.x, wB0.y, wB1.x, wB1.y, wB2.x, wB2.y};
            #pragma unroll
            for (int i = 0; i < 4; ++i)
                #pragma unroll
                for (int j = 0; j < 6; ++j)
                    fma2(acc[i][j], xv[i], wv[j]);
        }
    }

    // ---- epilogue ---------------------------------------------------------
    float bb[6];
    #pragma unroll
    for (int j = 0; j < 6; ++j) {
        int n = n0 + warp * 6 + j;
        bb[j] = (n < N_DIM) ? bias[n] : 0.0f;
    }
    #pragma unroll
    for (int i = 0; i < 4; ++i) {
        float lo[6], hi[6];
        #pragma unroll
        for (int j = 0; j < 6; ++j) unpack2(acc[i][j], lo[j], hi[j]);
        // i=0: rows 4l,4l+1 ; i=1: 4l+2,4l+3 ; i=2: +128 ; i=3: +130
        int r0 = m0 + 4 * lane + (i & 1) * 2 + (i >> 1) * 128;
        float* d0 = out + (size_t)r0 * N_DIM + n0 + warp * 6;
        float* d1 = d0 + N_DIM;
        #pragma unroll
        for (int j = 0; j < 3; ++j) {
            int n = n0 + warp * 6 + 2 * j;
            if (n + 1 < N_DIM) {
                *(float2*)(d0 + 2 * j) = make_float2(lo[2*j] + bb[2*j], lo[2*j+1] + bb[2*j+1]);
                *(float2*)(d1 + 2 * j) = make_float2(hi[2*j] + bb[2*j], hi[2*j+1] + bb[2*j+1]);
            } else if (n < N_DIM) {
                d0[2 * j] = lo[2 * j] + bb[2 * j];
                d1[2 * j] = hi[2 * j] + bb[2 * j];
            }
        }
    }
}

// ---------------------------------------------------------------------------
// 6. Heavy columns: full dense dot per (column, row-pair), overwrites output.
// ---------------------------------------------------------------------------
__global__ void dense_cols_kernel(const float* __restrict__ x,
                                  const float* __restrict__ W,
                                  const float* __restrict__ mask,
                                  const float* __restrict__ bias,
                                  float* __restrict__ out) {
    const int nh = g_nheavy;
    if (nh == 0) return;
    const int wflat = (blockIdx.x * blockDim.x + threadIdx.x) >> 5;  // 0..8191
    const int lane  = threadIdx.x & 31;
    const int units_per_col = M_DIM / 2;
    const int total = nh * units_per_col;
    for (int u = wflat; u < total; u += 8192) {
        int c   = g_heavy[u / units_per_col];
        int seg = u % units_per_col;
        int r0  = seg * 2;
        const float* wr = W    + (size_t)c * K_DIM;
        const float* mr = mask + (size_t)c * K_DIM;
        const float* x0 = x + (size_t)r0 * K_DIM;
        float s0 = 0.0f, s1 = 0.0f;
        #pragma unroll 4
        for (int k = lane; k < K_DIM; k += 32) {
            float wv = mr[k] * wr[k];
            s0 += x0[k] * wv;
            s1 += x0[K_DIM + k] * wv;
        }
        #pragma unroll
        for (int d = 16; d; d >>= 1) {
            s0 += __shfl_xor_sync(0xffffffffu, s0, d);
            s1 += __shfl_xor_sync(0xffffffffu, s1, d);
        }
        if (lane == 0) {
            float b = bias[c];
            out[(size_t)r0 * N_DIM + c]       = s0 + b;
            out[(size_t)(r0 + 1) * N_DIM + c] = s1 + b;
        }
    }
}

// ---------------------------------------------------------------------------
extern "C" void kernel_launch(void* const* d_in, const int* in_sizes, int n_in,
                              void* d_out, int out_size) {
    const float* x    = (const float*)d_in[0];  // [16384, 2048]
    const float* W    = (const float*)d_in[1];  // [8192, 2048]
    const float* bias = (const float*)d_in[2];  // [8192]
    const float* mask = (const float*)d_in[3];  // [8192, 2048]
    float* out = (float*)d_out;                 // [16384, 8192]

    float* xT = nullptr;
    cudaGetSymbolAddress((void**)&xT, g_xT);

    rowscan_kernel<<<N_DIM / 8, 256>>>(mask);
    tile_pack_kernel<<<NTILES, 256>>>(W, mask);
    heavy_list_kernel<<<1, 256>>>();
    {
        dim3 tb(32, 8);
        dim3 tg(K_DIM / 32, M_DIM / 32);
        transpose_kernel<<<tg, tb>>>(x, xT);
    }
    {
        dim3 grid(M_DIM / TM, NTILES);
        spmm_kernel<<<grid, 128>>>(xT, bias, out);
    }
    dense_cols_kernel<<<1024, 256>>>(x, W, mask, bias, out);
}